// round 1
// baseline (speedup 1.0000x reference)
#include <cuda_runtime.h>
#include <cuda_fp16.h>
#include <cstdint>

#define NV 200000
#define KK 27
#define CC 64
#define BM 128
#define BN_EPS 1e-5f

// ---------------- device scratch (static globals: allowed) ----------------
__device__ alignas(16) __half g_y[(size_t)NV * CC];        // fp16 activations (25.6 MB)
__device__ alignas(16) float  g_tmp[(size_t)NV * CC];      // conv1 output fp32 (51.2 MB)
__device__ alignas(16) __half g_Wh[2][KK * CC * CC];       // fp16 weights
__device__ float g_sum[2][CC];
__device__ float g_sumsq[2][CC];
__device__ float g_scale[2][CC];
__device__ float g_shift[2][CC];
__device__ int   g_is64;

// ---------------- init: zero stats + detect index dtype ----------------
__global__ void k_init(const void* __restrict__ nbr) {
    int t = threadIdx.x;
    if (t < CC) {
        g_sum[0][t] = 0.f; g_sum[1][t] = 0.f;
        g_sumsq[0][t] = 0.f; g_sumsq[1][t] = 0.f;
    }
    if (t == 0) {
        // If the buffer is really int64, every 8-byte word is a valid index.
        // If it's int32, pairs combine into huge values -> detect.
        const long long* p = (const long long*)nbr;
        int ok = 1;
        for (int i = 0; i < 64; ++i) {
            long long v = p[i];
            if (v < 0 || v >= NV) { ok = 0; break; }
        }
        g_is64 = ok;
    }
}

// ---------------- per-channel sum / sumsq ----------------
__global__ void k_colstats(const float* __restrict__ xin, int stage) {
    const float* v = stage ? (const float*)g_tmp : xin;
    __shared__ float sh[2][4][CC];
    int ch = threadIdx.x & 63;
    int rg = threadIdx.x >> 6;
    float s = 0.f, s2 = 0.f;
    for (int row = blockIdx.x * 4 + rg; row < NV; row += gridDim.x * 4) {
        float x = v[(size_t)row * CC + ch];
        s += x; s2 += x * x;
    }
    sh[0][rg][ch] = s; sh[1][rg][ch] = s2;
    __syncthreads();
    if (rg == 0) {
        s  = sh[0][0][ch] + sh[0][1][ch] + sh[0][2][ch] + sh[0][3][ch];
        s2 = sh[1][0][ch] + sh[1][1][ch] + sh[1][2][ch] + sh[1][3][ch];
        atomicAdd(&g_sum[stage][ch], s);
        atomicAdd(&g_sumsq[stage][ch], s2);
    }
}

__global__ void k_finalize(const float* __restrict__ gamma,
                           const float* __restrict__ beta, int stage) {
    int c = threadIdx.x;
    float mean = g_sum[stage][c] / (float)NV;
    float var  = g_sumsq[stage][c] / (float)NV - mean * mean;
    float s = gamma[c] * rsqrtf(var + BN_EPS);
    g_scale[stage][c] = s;
    g_shift[stage][c] = beta[c] - mean * s;
}

// ---------------- fused BN + ReLU + fp16 quantize ----------------
__global__ void k_bnrelu(const float* __restrict__ xin, int stage) {
    const float* v = stage ? (const float*)g_tmp : xin;
    const int total = NV * CC / 4;
    for (int i = blockIdx.x * blockDim.x + threadIdx.x; i < total;
         i += gridDim.x * blockDim.x) {
        float4 f = ((const float4*)v)[i];
        int cb = (i & 15) << 2;
        float s0 = g_scale[stage][cb + 0], s1 = g_scale[stage][cb + 1];
        float s2 = g_scale[stage][cb + 2], s3 = g_scale[stage][cb + 3];
        float t0 = g_shift[stage][cb + 0], t1 = g_shift[stage][cb + 1];
        float t2 = g_shift[stage][cb + 2], t3 = g_shift[stage][cb + 3];
        float a = fmaxf(fmaf(f.x, s0, t0), 0.f);
        float b = fmaxf(fmaf(f.y, s1, t1), 0.f);
        float c = fmaxf(fmaf(f.z, s2, t2), 0.f);
        float d = fmaxf(fmaf(f.w, s3, t3), 0.f);
        __half2 h0 = __floats2half2_rn(a, b);
        __half2 h1 = __floats2half2_rn(c, d);
        ((__half2*)g_y)[2 * i]     = h0;
        ((__half2*)g_y)[2 * i + 1] = h1;
    }
}

// ---------------- weight fp16 conversion ----------------
__global__ void k_wcvt(const float* __restrict__ W1, const float* __restrict__ W2) {
    const int total = KK * CC * CC;
    for (int i = blockIdx.x * blockDim.x + threadIdx.x; i < total;
         i += gridDim.x * blockDim.x) {
        g_Wh[0][i] = __float2half_rn(W1[i]);
        g_Wh[1][i] = __float2half_rn(W2[i]);
    }
}

// ---------------- gather-GEMM conv (HMMA) ----------------
__device__ __forceinline__ uint32_t smem_u32(const void* p) {
    return (uint32_t)__cvta_generic_to_shared(p);
}

__global__ void __launch_bounds__(256, 2)
k_conv(const void* __restrict__ nbr, int which,
       const float* __restrict__ residual, float* __restrict__ dout)
{
    __shared__ alignas(16) __half sA[BM][72];   // gathered rows, 72-halve pitch (conflict-free)
    __shared__ alignas(16) __half sB[CC][72];   // W[k] as [ci][co]

    const __half* __restrict__ Wh = g_Wh[which];
    float* __restrict__ out = which ? dout : (float*)g_tmp;

    const int tid = threadIdx.x;
    const int warp = tid >> 5, lane = tid & 31;
    const int wm = warp >> 1;    // 0..3 -> 32-row slab
    const int wn = warp & 1;     // 0..1 -> 32-col slab
    const int m0 = blockIdx.x * BM;
    const bool is64 = (g_is64 != 0);

    float acc[2][4][4];
    #pragma unroll
    for (int a = 0; a < 2; ++a)
        #pragma unroll
        for (int b = 0; b < 4; ++b)
            #pragma unroll
            for (int c = 0; c < 4; ++c) acc[a][b][c] = 0.f;

    // gather assignment: 2 threads per row, each copies 64 B
    const int r  = tid >> 1;
    const int hs = tid & 1;
    const int gn = (m0 + r < NV) ? (m0 + r) : 0;

    for (int k = 0; k < KK; ++k) {
        __syncthreads();
        // ---- gather A tile: 128 rows x 64 half ----
        {
            long long pos = (long long)gn * KK + k;
            long long gi = is64 ? ((const long long*)nbr)[pos]
                                : (long long)((const int*)nbr)[pos];
            const int4* src = (const int4*)(g_y + gi * CC) + hs * 4;
            int4* dst = (int4*)(&sA[r][0]) + hs * 4;
            #pragma unroll
            for (int j = 0; j < 4; ++j) dst[j] = src[j];
        }
        // ---- load B tile: W[k] 64x64 half ----
        {
            const int4* wsrc = (const int4*)(Wh + k * CC * CC);
            #pragma unroll
            for (int j = 0; j < 2; ++j) {
                int c2 = tid + j * 256;
                ((int4*)(&sB[c2 >> 3][0]))[c2 & 7] = wsrc[c2];
            }
        }
        __syncthreads();

        // ---- 4 x k16 MMA steps over the 64-wide K slice ----
        #pragma unroll
        for (int ks = 0; ks < 4; ++ks) {
            const int k0 = ks * 16;
            uint32_t a0[4], a1[4];
            {
                int row = wm * 32 + (lane & 15);
                int col = k0 + (lane >> 4) * 8;
                uint32_t ad = smem_u32(&sA[row][col]);
                asm volatile("ldmatrix.sync.aligned.m8n8.x4.shared.b16 {%0,%1,%2,%3}, [%4];"
                             : "=r"(a0[0]), "=r"(a0[1]), "=r"(a0[2]), "=r"(a0[3]) : "r"(ad));
                ad = smem_u32(&sA[row + 16][col]);
                asm volatile("ldmatrix.sync.aligned.m8n8.x4.shared.b16 {%0,%1,%2,%3}, [%4];"
                             : "=r"(a1[0]), "=r"(a1[1]), "=r"(a1[2]), "=r"(a1[3]) : "r"(ad));
            }
            uint32_t b0[4], b1[4];
            {
                int krow = k0 + ((lane >> 3) & 1) * 8 + (lane & 7);
                int coll = wn * 32 + (lane >> 4) * 8;
                uint32_t ad = smem_u32(&sB[krow][coll]);
                asm volatile("ldmatrix.sync.aligned.m8n8.x4.trans.shared.b16 {%0,%1,%2,%3}, [%4];"
                             : "=r"(b0[0]), "=r"(b0[1]), "=r"(b0[2]), "=r"(b0[3]) : "r"(ad));
                ad = smem_u32(&sB[krow][coll + 16]);
                asm volatile("ldmatrix.sync.aligned.m8n8.x4.trans.shared.b16 {%0,%1,%2,%3}, [%4];"
                             : "=r"(b1[0]), "=r"(b1[1]), "=r"(b1[2]), "=r"(b1[3]) : "r"(ad));
            }
            #pragma unroll
            for (int mt = 0; mt < 2; ++mt) {
                const uint32_t* A = mt ? a1 : a0;
                #pragma unroll
                for (int nt = 0; nt < 4; ++nt) {
                    const uint32_t* B = (nt < 2) ? b0 : b1;
                    uint32_t bb0 = B[(nt & 1) * 2], bb1 = B[(nt & 1) * 2 + 1];
                    float* C = acc[mt][nt];
                    asm volatile(
                        "mma.sync.aligned.m16n8k16.row.col.f32.f16.f16.f32 "
                        "{%0,%1,%2,%3}, {%4,%5,%6,%7}, {%8,%9}, {%0,%1,%2,%3};"
                        : "+f"(C[0]), "+f"(C[1]), "+f"(C[2]), "+f"(C[3])
                        : "r"(A[0]), "r"(A[1]), "r"(A[2]), "r"(A[3]),
                          "r"(bb0), "r"(bb1));
                }
            }
        }
    }

    // ---- epilogue (fused residual for conv2) ----
    #pragma unroll
    for (int mt = 0; mt < 2; ++mt) {
        int rbase = m0 + wm * 32 + mt * 16 + (lane >> 2);
        #pragma unroll
        for (int nt = 0; nt < 4; ++nt) {
            int col = wn * 32 + nt * 8 + (lane & 3) * 2;
            float* C = acc[mt][nt];
            if (rbase < NV) {
                size_t o = (size_t)rbase * CC + col;
                float v0 = C[0], v1 = C[1];
                if (residual) { v0 += residual[o]; v1 += residual[o + 1]; }
                out[o] = v0; out[o + 1] = v1;
            }
            if (rbase + 8 < NV) {
                size_t o = (size_t)(rbase + 8) * CC + col;
                float v2 = C[2], v3 = C[3];
                if (residual) { v2 += residual[o]; v3 += residual[o + 1]; }
                out[o] = v2; out[o + 1] = v3;
            }
        }
    }
}

// ---------------- launch ----------------
extern "C" void kernel_launch(void* const* d_in, const int* in_sizes, int n_in,
                              void* d_out, int out_size) {
    const float* x      = (const float*)d_in[0];
    const void*  nbr    = d_in[1];
    const float* W1     = (const float*)d_in[2];
    const float* gamma1 = (const float*)d_in[3];
    const float* beta1  = (const float*)d_in[4];
    const float* W2     = (const float*)d_in[5];
    const float* gamma2 = (const float*)d_in[6];
    const float* beta2  = (const float*)d_in[7];
    float* out = (float*)d_out;

    const int conv_grid = (NV + BM - 1) / BM;

    k_init<<<1, 64>>>(nbr);
    k_wcvt<<<432, 256>>>(W1, W2);

    // stage 1
    k_colstats<<<512, 256>>>(x, 0);
    k_finalize<<<1, 64>>>(gamma1, beta1, 0);
    k_bnrelu<<<2048, 256>>>(x, 0);
    k_conv<<<conv_grid, 256>>>(nbr, 0, nullptr, nullptr);

    // stage 2
    k_colstats<<<512, 256>>>(nullptr, 1);
    k_finalize<<<1, 64>>>(gamma2, beta2, 1);
    k_bnrelu<<<2048, 256>>>(nullptr, 1);
    k_conv<<<conv_grid, 256>>>(nbr, 1, x, out);
}

// round 2
// speedup vs baseline: 1.0399x; 1.0399x over previous
#include <cuda_runtime.h>
#include <cuda_fp16.h>
#include <cstdint>

#define NV 200000
#define KK 27
#define CC 64
#define BM 128
#define PITCH 72
#define STAGES 3
#define BN_EPS 1e-5f

// ---------------- device scratch ----------------
__device__ alignas(16) __half g_y[(size_t)NV * CC];        // fp16 activations (25.6 MB)
__device__ alignas(16) float  g_tmp[(size_t)NV * CC];      // conv1 output fp32 (51.2 MB)
__device__ alignas(16) __half g_Wh[2][KK * CC * CC];       // fp16 weights
__device__ float g_sum[2][CC];
__device__ float g_sumsq[2][CC];
__device__ float g_scale[2][CC];
__device__ float g_shift[2][CC];
__device__ int   g_is64;

// ---------------- init: zero stats + detect index dtype ----------------
__global__ void k_init(const void* __restrict__ nbr) {
    int t = threadIdx.x;
    if (t < CC) {
        g_sum[0][t] = 0.f; g_sum[1][t] = 0.f;
        g_sumsq[0][t] = 0.f; g_sumsq[1][t] = 0.f;
    }
    if (t == 0) {
        const long long* p = (const long long*)nbr;
        int ok = 1;
        for (int i = 0; i < 64; ++i) {
            long long v = p[i];
            if (v < 0 || v >= NV) { ok = 0; break; }
        }
        g_is64 = ok;
    }
}

// ---------------- per-channel sum / sumsq ----------------
__global__ void k_colstats(const float* __restrict__ xin, int stage) {
    const float* v = stage ? (const float*)g_tmp : xin;
    __shared__ float sh[2][4][CC];
    int ch = threadIdx.x & 63;
    int rg = threadIdx.x >> 6;
    float s = 0.f, s2 = 0.f;
    for (int row = blockIdx.x * 4 + rg; row < NV; row += gridDim.x * 4) {
        float x = v[(size_t)row * CC + ch];
        s += x; s2 += x * x;
    }
    sh[0][rg][ch] = s; sh[1][rg][ch] = s2;
    __syncthreads();
    if (rg == 0) {
        s  = sh[0][0][ch] + sh[0][1][ch] + sh[0][2][ch] + sh[0][3][ch];
        s2 = sh[1][0][ch] + sh[1][1][ch] + sh[1][2][ch] + sh[1][3][ch];
        atomicAdd(&g_sum[stage][ch], s);
        atomicAdd(&g_sumsq[stage][ch], s2);
    }
}

__global__ void k_finalize(const float* __restrict__ gamma,
                           const float* __restrict__ beta, int stage) {
    int c = threadIdx.x;
    float mean = g_sum[stage][c] / (float)NV;
    float var  = g_sumsq[stage][c] / (float)NV - mean * mean;
    float s = gamma[c] * rsqrtf(var + BN_EPS);
    g_scale[stage][c] = s;
    g_shift[stage][c] = beta[c] - mean * s;
}

// ---------------- fused BN + ReLU + fp16 quantize ----------------
__global__ void k_bnrelu(const float* __restrict__ xin, int stage) {
    const float* v = stage ? (const float*)g_tmp : xin;
    const int total = NV * CC / 4;
    for (int i = blockIdx.x * blockDim.x + threadIdx.x; i < total;
         i += gridDim.x * blockDim.x) {
        float4 f = ((const float4*)v)[i];
        int cb = (i & 15) << 2;
        float s0 = g_scale[stage][cb + 0], s1 = g_scale[stage][cb + 1];
        float s2 = g_scale[stage][cb + 2], s3 = g_scale[stage][cb + 3];
        float t0 = g_shift[stage][cb + 0], t1 = g_shift[stage][cb + 1];
        float t2 = g_shift[stage][cb + 2], t3 = g_shift[stage][cb + 3];
        float a = fmaxf(fmaf(f.x, s0, t0), 0.f);
        float b = fmaxf(fmaf(f.y, s1, t1), 0.f);
        float c = fmaxf(fmaf(f.z, s2, t2), 0.f);
        float d = fmaxf(fmaf(f.w, s3, t3), 0.f);
        ((__half2*)g_y)[2 * i]     = __floats2half2_rn(a, b);
        ((__half2*)g_y)[2 * i + 1] = __floats2half2_rn(c, d);
    }
}

// ---------------- weight fp16 conversion ----------------
__global__ void k_wcvt(const float* __restrict__ W1, const float* __restrict__ W2) {
    const int total = KK * CC * CC;
    for (int i = blockIdx.x * blockDim.x + threadIdx.x; i < total;
         i += gridDim.x * blockDim.x) {
        g_Wh[0][i] = __float2half_rn(W1[i]);
        g_Wh[1][i] = __float2half_rn(W2[i]);
    }
}

// ---------------- helpers ----------------
__device__ __forceinline__ uint32_t smem_u32(const void* p) {
    return (uint32_t)__cvta_generic_to_shared(p);
}
__device__ __forceinline__ void cp16(uint32_t dst, const void* src) {
    asm volatile("cp.async.cg.shared.global [%0], [%1], 16;\n" :: "r"(dst), "l"(src));
}
__device__ __forceinline__ int ld_idx(const void* nbr, bool is64, int gn, int k) {
    size_t pos = (size_t)gn * KK + k;
    return is64 ? (int)((const long long*)nbr)[pos] : ((const int*)nbr)[pos];
}

// ---------------- pipelined gather-GEMM conv (HMMA + cp.async) ----------------
__global__ void __launch_bounds__(256, 2)
k_conv(const void* __restrict__ nbr, int which,
       const float* __restrict__ residual, float* __restrict__ dout)
{
    extern __shared__ __half sh[];
    __half* sAb = sh;                          // [STAGES][BM][PITCH]
    __half* sBb = sh + STAGES * BM * PITCH;    // [STAGES][CC][PITCH]

    const __half* __restrict__ Wh = g_Wh[which];
    float* __restrict__ out = which ? dout : (float*)g_tmp;

    const int tid = threadIdx.x;
    const int warp = tid >> 5, lane = tid & 31;
    const int wm = warp >> 1;
    const int wn = warp & 1;
    const int m0 = blockIdx.x * BM;
    const bool is64 = (g_is64 != 0);

    float acc[2][4][4];
    #pragma unroll
    for (int a = 0; a < 2; ++a)
        #pragma unroll
        for (int b = 0; b < 4; ++b)
            #pragma unroll
            for (int c = 0; c < 4; ++c) acc[a][b][c] = 0.f;

    // gather assignment: 2 threads per row, each copies 64 B (4 x 16B)
    const int r  = tid >> 1;
    const int hs = tid & 1;
    const int gn = (m0 + r < NV) ? (m0 + r) : 0;

    // issue one stage: A gather row + B weight tile slice
    auto issue = [&](int stage, int gi, int k) {
        const __half* srcA = g_y + (size_t)gi * CC + hs * 32;
        uint32_t dstA = smem_u32(sAb + ((stage * BM + r) * PITCH) + hs * 32);
        #pragma unroll
        for (int j = 0; j < 4; ++j) cp16(dstA + j * 16, srcA + j * 8);
        const __half* wsrc = Wh + k * CC * CC;
        #pragma unroll
        for (int j = 0; j < 2; ++j) {
            int c2 = tid + j * 256;                 // 512 chunks of 16B
            int row = c2 >> 3, off = (c2 & 7) * 8;
            uint32_t dstB = smem_u32(sBb + ((stage * CC + row) * PITCH) + off);
            cp16(dstB, wsrc + c2 * 8);
        }
    };

    // prologue: stages 0 and 1 in flight
    int gi0 = ld_idx(nbr, is64, gn, 0);
    int gi1 = ld_idx(nbr, is64, gn, 1);
    issue(0, gi0, 0);
    asm volatile("cp.async.commit_group;\n");
    issue(1, gi1, 1);
    asm volatile("cp.async.commit_group;\n");
    int gi_a = ld_idx(nbr, is64, gn, 2);
    int gi_b = ld_idx(nbr, is64, gn, 3);

    int st = 0;
    for (int k = 0; k < KK; ++k) {
        asm volatile("cp.async.wait_group 1;\n");
        __syncthreads();
        // prefetch k+2 into the stage freed by mma(k-1)
        if (k + 2 < KK) {
            int st2 = st + 2; if (st2 >= STAGES) st2 -= STAGES;
            issue(st2, gi_a, k + 2);
        }
        asm volatile("cp.async.commit_group;\n");
        gi_a = gi_b;
        int knext = k + 4 < KK ? k + 4 : KK - 1;
        gi_b = ld_idx(nbr, is64, gn, knext);

        const __half* sA = sAb + st * BM * PITCH;
        const __half* sB = sBb + st * CC * PITCH;

        #pragma unroll
        for (int ks = 0; ks < 4; ++ks) {
            const int k0 = ks * 16;
            uint32_t a0[4], a1[4];
            {
                int row = wm * 32 + (lane & 15);
                int col = k0 + (lane >> 4) * 8;
                uint32_t ad = smem_u32(sA + row * PITCH + col);
                asm volatile("ldmatrix.sync.aligned.m8n8.x4.shared.b16 {%0,%1,%2,%3}, [%4];"
                             : "=r"(a0[0]), "=r"(a0[1]), "=r"(a0[2]), "=r"(a0[3]) : "r"(ad));
                ad = smem_u32(sA + (row + 16) * PITCH + col);
                asm volatile("ldmatrix.sync.aligned.m8n8.x4.shared.b16 {%0,%1,%2,%3}, [%4];"
                             : "=r"(a1[0]), "=r"(a1[1]), "=r"(a1[2]), "=r"(a1[3]) : "r"(ad));
            }
            uint32_t b0[4], b1[4];
            {
                int krow = k0 + ((lane >> 3) & 1) * 8 + (lane & 7);
                int coll = wn * 32 + (lane >> 4) * 8;
                uint32_t ad = smem_u32(sB + krow * PITCH + coll);
                asm volatile("ldmatrix.sync.aligned.m8n8.x4.trans.shared.b16 {%0,%1,%2,%3}, [%4];"
                             : "=r"(b0[0]), "=r"(b0[1]), "=r"(b0[2]), "=r"(b0[3]) : "r"(ad));
                ad = smem_u32(sB + krow * PITCH + coll + 16);
                asm volatile("ldmatrix.sync.aligned.m8n8.x4.trans.shared.b16 {%0,%1,%2,%3}, [%4];"
                             : "=r"(b1[0]), "=r"(b1[1]), "=r"(b1[2]), "=r"(b1[3]) : "r"(ad));
            }
            #pragma unroll
            for (int mt = 0; mt < 2; ++mt) {
                const uint32_t* A = mt ? a1 : a0;
                #pragma unroll
                for (int nt = 0; nt < 4; ++nt) {
                    const uint32_t* B = (nt < 2) ? b0 : b1;
                    uint32_t bb0 = B[(nt & 1) * 2], bb1 = B[(nt & 1) * 2 + 1];
                    float* C = acc[mt][nt];
                    asm volatile(
                        "mma.sync.aligned.m16n8k16.row.col.f32.f16.f16.f32 "
                        "{%0,%1,%2,%3}, {%4,%5,%6,%7}, {%8,%9}, {%0,%1,%2,%3};"
                        : "+f"(C[0]), "+f"(C[1]), "+f"(C[2]), "+f"(C[3])
                        : "r"(A[0]), "r"(A[1]), "r"(A[2]), "r"(A[3]),
                          "r"(bb0), "r"(bb1));
                }
            }
        }
        if (++st >= STAGES) st = 0;
    }

    // ---- epilogue (fused residual for conv2) ----
    #pragma unroll
    for (int mt = 0; mt < 2; ++mt) {
        int rbase = m0 + wm * 32 + mt * 16 + (lane >> 2);
        #pragma unroll
        for (int nt = 0; nt < 4; ++nt) {
            int col = wn * 32 + nt * 8 + (lane & 3) * 2;
            float* C = acc[mt][nt];
            if (rbase < NV) {
                size_t o = (size_t)rbase * CC + col;
                float v0 = C[0], v1 = C[1];
                if (residual) { v0 += residual[o]; v1 += residual[o + 1]; }
                out[o] = v0; out[o + 1] = v1;
            }
            if (rbase + 8 < NV) {
                size_t o = (size_t)(rbase + 8) * CC + col;
                float v2 = C[2], v3 = C[3];
                if (residual) { v2 += residual[o]; v3 += residual[o + 1]; }
                out[o] = v2; out[o + 1] = v3;
            }
        }
    }
}

// ---------------- launch ----------------
extern "C" void kernel_launch(void* const* d_in, const int* in_sizes, int n_in,
                              void* d_out, int out_size) {
    const float* x      = (const float*)d_in[0];
    const void*  nbr    = d_in[1];
    const float* W1     = (const float*)d_in[2];
    const float* gamma1 = (const float*)d_in[3];
    const float* beta1  = (const float*)d_in[4];
    const float* W2     = (const float*)d_in[5];
    const float* gamma2 = (const float*)d_in[6];
    const float* beta2  = (const float*)d_in[7];
    float* out = (float*)d_out;

    const int conv_grid = (NV + BM - 1) / BM;
    const int smem_bytes = STAGES * (BM + CC) * PITCH * sizeof(__half);  // 82944

    static int attr_set = 0;
    if (!attr_set) {
        cudaFuncSetAttribute(k_conv, cudaFuncAttributeMaxDynamicSharedMemorySize, smem_bytes);
        attr_set = 1;
    }

    k_init<<<1, 64>>>(nbr);
    k_wcvt<<<432, 256>>>(W1, W2);

    // stage 1
    k_colstats<<<512, 256>>>(x, 0);
    k_finalize<<<1, 64>>>(gamma1, beta1, 0);
    k_bnrelu<<<2048, 256>>>(x, 0);
    k_conv<<<conv_grid, 256, smem_bytes>>>(nbr, 0, nullptr, nullptr);

    // stage 2
    k_colstats<<<512, 256>>>(nullptr, 1);
    k_finalize<<<1, 64>>>(gamma2, beta2, 1);
    k_bnrelu<<<2048, 256>>>(nullptr, 1);
    k_conv<<<conv_grid, 256, smem_bytes>>>(nbr, 1, x, out);
}

// round 4
// speedup vs baseline: 1.2740x; 1.2251x over previous
#include <cuda_runtime.h>
#include <cuda_fp16.h>
#include <cstdint>

#define NV 200000
#define KK 27
#define CC 64
#define BM 128
#define STAGES 3
#define BN_EPS 1e-5f

#define A_BYTES (BM * 128)              // 16384 (128B swizzled rows)
#define B_BYTES (CC * 128)              // 8192
#define STAGE_BYTES (A_BYTES + B_BYTES) // 24576
#define SMEM_TOTAL (STAGES * STAGE_BYTES)  // 73728 -> 3 CTAs/SM

#define SW(o) ((o) ^ (((o) >> 3) & 0x70))

// ---------------- device scratch ----------------
__device__ alignas(256) __half g_y[(size_t)NV * CC];     // fp16 activations
__device__ alignas(256) float  g_tmp[(size_t)NV * CC];   // conv1 output fp32
__device__ alignas(256) __half g_Wh[2][KK * CC * CC];    // fp16 weights, pre-swizzled [ci][co]
__device__ float g_sum[2][CC];
__device__ float g_sumsq[2][CC];
__device__ float g_scale[2][CC];
__device__ float g_shift[2][CC];
__device__ int   g_is64;

// ---------------- helpers ----------------
__device__ __forceinline__ uint32_t smem_u32(const void* p) {
    return (uint32_t)__cvta_generic_to_shared(p);
}
__device__ __forceinline__ void cp16(uint32_t dst, const void* src) {
    asm volatile("cp.async.cg.shared.global [%0], [%1], 16;\n" :: "r"(dst), "l"(src));
}
__device__ __forceinline__ int ld_idx(const void* nbr, bool is64, int gn, int k) {
    size_t pos = (size_t)gn * KK + k;
    return is64 ? (int)((const long long*)nbr)[pos] : ((const int*)nbr)[pos];
}

// ---------------- init ----------------
__global__ void k_init(const void* __restrict__ nbr) {
    int t = threadIdx.x;
    if (t < CC) {
        g_sum[0][t] = 0.f; g_sum[1][t] = 0.f;
        g_sumsq[0][t] = 0.f; g_sumsq[1][t] = 0.f;
    }
    if (t == 0) {
        const long long* p = (const long long*)nbr;
        int ok = 1;
        for (int i = 0; i < 64; ++i) {
            long long v = p[i];
            if (v < 0 || v >= NV) { ok = 0; break; }
        }
        g_is64 = ok;
    }
}

__global__ void k_nop() {}

// ---------------- per-channel sum / sumsq ----------------
__global__ void k_colstats(const float* __restrict__ xin, int stage) {
    const float* v = stage ? (const float*)g_tmp : xin;
    __shared__ float sh[2][4][CC];
    int ch = threadIdx.x & 63;
    int rg = threadIdx.x >> 6;
    float s = 0.f, s2 = 0.f;
    for (int row = blockIdx.x * 4 + rg; row < NV; row += gridDim.x * 4) {
        float x = v[(size_t)row * CC + ch];
        s += x; s2 += x * x;
    }
    sh[0][rg][ch] = s; sh[1][rg][ch] = s2;
    __syncthreads();
    if (rg == 0) {
        s  = sh[0][0][ch] + sh[0][1][ch] + sh[0][2][ch] + sh[0][3][ch];
        s2 = sh[1][0][ch] + sh[1][1][ch] + sh[1][2][ch] + sh[1][3][ch];
        atomicAdd(&g_sum[stage][ch], s);
        atomicAdd(&g_sumsq[stage][ch], s2);
    }
}

__global__ void k_finalize(const float* __restrict__ gamma,
                           const float* __restrict__ beta, int stage) {
    int c = threadIdx.x;
    float mean = g_sum[stage][c] / (float)NV;
    float var  = g_sumsq[stage][c] / (float)NV - mean * mean;
    float s = gamma[c] * rsqrtf(var + BN_EPS);
    g_scale[stage][c] = s;
    g_shift[stage][c] = beta[c] - mean * s;
}

// ---------------- fused BN + ReLU + fp16 quantize ----------------
__global__ void k_bnrelu(const float* __restrict__ xin, int stage) {
    const float* v = stage ? (const float*)g_tmp : xin;
    const int total = NV * CC / 4;
    for (int i = blockIdx.x * blockDim.x + threadIdx.x; i < total;
         i += gridDim.x * blockDim.x) {
        float4 f = ((const float4*)v)[i];
        int cb = (i & 15) << 2;
        float s0 = g_scale[stage][cb + 0], s1 = g_scale[stage][cb + 1];
        float s2 = g_scale[stage][cb + 2], s3 = g_scale[stage][cb + 3];
        float t0 = g_shift[stage][cb + 0], t1 = g_shift[stage][cb + 1];
        float t2 = g_shift[stage][cb + 2], t3 = g_shift[stage][cb + 3];
        float a = fmaxf(fmaf(f.x, s0, t0), 0.f);
        float b = fmaxf(fmaf(f.y, s1, t1), 0.f);
        float c = fmaxf(fmaf(f.z, s2, t2), 0.f);
        float d = fmaxf(fmaf(f.w, s3, t3), 0.f);
        ((__half2*)g_y)[2 * i]     = __floats2half2_rn(a, b);
        ((__half2*)g_y)[2 * i + 1] = __floats2half2_rn(c, d);
    }
}

// ---------------- weight convert: fp16 + SW128 pre-swizzle ([ci][co] rows) ----------------
__global__ void k_wcvt(const float* __restrict__ W1, const float* __restrict__ W2) {
    const int total = KK * CC * CC;
    for (int i = blockIdx.x * blockDim.x + threadIdx.x; i < total;
         i += gridDim.x * blockDim.x) {
        int k  = i >> 12;
        int ci = (i & 4095) >> 6;
        int co = i & 63;
        uint32_t off = (uint32_t)SW(ci * 128 + co * 2) >> 1;
        g_Wh[0][k * 4096 + off] = __float2half_rn(W1[i]);
        g_Wh[1][k * 4096 + off] = __float2half_rn(W2[i]);
    }
}

// ---------------- pipelined gather-GEMM conv (HMMA, swizzled smem, occ 3) ----------------
__global__ void __launch_bounds__(256, 3)
k_conv(const void* __restrict__ nbr, int which,
       const float* __restrict__ residual, float* __restrict__ dout)
{
    extern __shared__ char smem[];
    const uint32_t sb = smem_u32(smem);

    const __half* __restrict__ Wh = g_Wh[which];
    float* __restrict__ out = which ? dout : (float*)g_tmp;

    const int tid = threadIdx.x;
    const int warp = tid >> 5, lane = tid & 31;
    const int wm = warp >> 1;
    const int wn = warp & 1;
    const int m0 = blockIdx.x * BM;
    const bool is64 = (g_is64 != 0);

    float acc[2][4][4];
    #pragma unroll
    for (int a = 0; a < 2; ++a)
        #pragma unroll
        for (int b = 0; b < 4; ++b)
            #pragma unroll
            for (int c = 0; c < 4; ++c) acc[a][b][c] = 0.f;

    // gather: 2 threads per A row, 64B each
    const int r  = tid >> 1;
    const int hs = tid & 1;
    const int gn = (m0 + r < NV) ? (m0 + r) : 0;

    auto fill = [&](int st, int gi, int k) {
        const __half* srcA = g_y + (size_t)gi * CC + hs * 32;
        uint32_t abase = sb + st * STAGE_BYTES;
        #pragma unroll
        for (int j = 0; j < 4; ++j) {
            uint32_t boff = (uint32_t)(r * 128 + (hs * 4 + j) * 16);
            cp16(abase + SW(boff), srcA + j * 8);
        }
        const __half* srcB = Wh + k * 4096;
        uint32_t bbase = abase + A_BYTES;
        cp16(bbase + tid * 16,         srcB + tid * 8);
        cp16(bbase + (tid + 256) * 16, srcB + (tid + 256) * 8);
    };

    // prologue
    {
        int i0 = ld_idx(nbr, is64, gn, 0);
        int i1 = ld_idx(nbr, is64, gn, 1);
        fill(0, i0, 0);
        asm volatile("cp.async.commit_group;\n");
        fill(1, i1, 1);
        asm volatile("cp.async.commit_group;\n");
    }
    int gi_a = ld_idx(nbr, is64, gn, 2);
    int gi_b = ld_idx(nbr, is64, gn, 3);

    int st = 0;
    for (int k = 0; k < KK; ++k) {
        asm volatile("cp.async.wait_group 1;\n");
        __syncthreads();
        if (k + 2 < KK) {
            int st2 = st + 2; if (st2 >= STAGES) st2 -= STAGES;
            fill(st2, gi_a, k + 2);
        }
        asm volatile("cp.async.commit_group;\n");
        gi_a = gi_b;
        gi_b = ld_idx(nbr, is64, gn, (k + 4 < KK) ? (k + 4) : (KK - 1));

        const uint32_t abase = sb + st * STAGE_BYTES;
        const uint32_t bbase = abase + A_BYTES;

        #pragma unroll
        for (int ks = 0; ks < 4; ++ks) {
            const int k0 = ks * 16;
            uint32_t a0[4], a1[4];
            {
                int row = wm * 32 + (lane & 15);
                int col = k0 + (lane >> 4) * 8;
                uint32_t ad = abase + SW((uint32_t)(row * 128 + col * 2));
                asm volatile("ldmatrix.sync.aligned.m8n8.x4.shared.b16 {%0,%1,%2,%3}, [%4];"
                             : "=r"(a0[0]), "=r"(a0[1]), "=r"(a0[2]), "=r"(a0[3]) : "r"(ad));
                ad = abase + SW((uint32_t)((row + 16) * 128 + col * 2));
                asm volatile("ldmatrix.sync.aligned.m8n8.x4.shared.b16 {%0,%1,%2,%3}, [%4];"
                             : "=r"(a1[0]), "=r"(a1[1]), "=r"(a1[2]), "=r"(a1[3]) : "r"(ad));
            }
            uint32_t b0[4], b1[4];
            {
                int krow = k0 + ((lane >> 3) & 1) * 8 + (lane & 7);
                int coll = wn * 32 + (lane >> 4) * 8;
                uint32_t ad = bbase + SW((uint32_t)(krow * 128 + coll * 2));
                asm volatile("ldmatrix.sync.aligned.m8n8.x4.trans.shared.b16 {%0,%1,%2,%3}, [%4];"
                             : "=r"(b0[0]), "=r"(b0[1]), "=r"(b0[2]), "=r"(b0[3]) : "r"(ad));
                ad = bbase + SW((uint32_t)(krow * 128 + (coll + 16) * 2));
                asm volatile("ldmatrix.sync.aligned.m8n8.x4.trans.shared.b16 {%0,%1,%2,%3}, [%4];"
                             : "=r"(b1[0]), "=r"(b1[1]), "=r"(b1[2]), "=r"(b1[3]) : "r"(ad));
            }
            #pragma unroll
            for (int mt = 0; mt < 2; ++mt) {
                const uint32_t* A = mt ? a1 : a0;
                #pragma unroll
                for (int nt = 0; nt < 4; ++nt) {
                    const uint32_t* B = (nt < 2) ? b0 : b1;
                    uint32_t bb0 = B[(nt & 1) * 2], bb1 = B[(nt & 1) * 2 + 1];
                    float* C = acc[mt][nt];
                    asm volatile(
                        "mma.sync.aligned.m16n8k16.row.col.f32.f16.f16.f32 "
                        "{%0,%1,%2,%3}, {%4,%5,%6,%7}, {%8,%9}, {%0,%1,%2,%3};"
                        : "+f"(C[0]), "+f"(C[1]), "+f"(C[2]), "+f"(C[3])
                        : "r"(A[0]), "r"(A[1]), "r"(A[2]), "r"(A[3]),
                          "r"(bb0), "r"(bb1));
                }
            }
        }
        if (++st >= STAGES) st = 0;
    }

    // ---- epilogue (fused residual for conv2) ----
    #pragma unroll
    for (int mt = 0; mt < 2; ++mt) {
        int rbase = m0 + wm * 32 + mt * 16 + (lane >> 2);
        #pragma unroll
        for (int nt = 0; nt < 4; ++nt) {
            int col = wn * 32 + nt * 8 + (lane & 3) * 2;
            float* C = acc[mt][nt];
            if (rbase < NV) {
                size_t o = (size_t)rbase * CC + col;
                float v0 = C[0], v1 = C[1];
                if (residual) { v0 += residual[o]; v1 += residual[o + 1]; }
                out[o] = v0; out[o + 1] = v1;
            }
            if (rbase + 8 < NV) {
                size_t o = (size_t)(rbase + 8) * CC + col;
                float v2 = C[2], v3 = C[3];
                if (residual) { v2 += residual[o]; v3 += residual[o + 1]; }
                out[o] = v2; out[o + 1] = v3;
            }
        }
    }
}

// ---------------- launch ----------------
extern "C" void kernel_launch(void* const* d_in, const int* in_sizes, int n_in,
                              void* d_out, int out_size) {
    const float* x      = (const float*)d_in[0];
    const void*  nbr    = d_in[1];
    const float* W1     = (const float*)d_in[2];
    const float* gamma1 = (const float*)d_in[3];
    const float* beta1  = (const float*)d_in[4];
    const float* W2     = (const float*)d_in[5];
    const float* gamma2 = (const float*)d_in[6];
    const float* beta2  = (const float*)d_in[7];
    float* out = (float*)d_out;

    const int conv_grid = (NV + BM - 1) / BM;

    static int attr_set = 0;
    if (!attr_set) {
        cudaFuncSetAttribute(k_conv, cudaFuncAttributeMaxDynamicSharedMemorySize,
                             SMEM_TOTAL);
        attr_set = 1;
    }

    k_init<<<1, 64>>>(nbr);          // launch 1
    k_wcvt<<<432, 256>>>(W1, W2);    // launch 2

    // stage 1
    k_colstats<<<512, 256>>>(x, 0);              // 3
    k_finalize<<<1, 64>>>(gamma1, beta1, 0);     // 4
    k_bnrelu<<<2048, 256>>>(x, 0);               // 5
    k_nop<<<1, 32>>>();                          // 6 (ncu alignment)
    k_nop<<<1, 32>>>();                          // 7 (ncu alignment)
    k_conv<<<conv_grid, 256, SMEM_TOTAL>>>(nbr, 0, nullptr, nullptr);  // 8 <- ncu target

    // stage 2
    k_colstats<<<512, 256>>>(nullptr, 1);
    k_finalize<<<1, 64>>>(gamma2, beta2, 1);
    k_bnrelu<<<2048, 256>>>(nullptr, 1);
    k_conv<<<conv_grid, 256, SMEM_TOTAL>>>(nbr, 1, x, out);
}

// round 5
// speedup vs baseline: 1.3588x; 1.0666x over previous
#include <cuda_runtime.h>
#include <cuda_fp16.h>
#include <cstdint>

#define NV 200000
#define KK 27
#define CC 64
#define BM 128
#define STAGES 2
#define BN_EPS 1e-5f

#define A_BYTES (BM * 128)
#define B_BYTES (CC * 128)
#define STAGE_BYTES (A_BYTES + B_BYTES)           // 24576
#define SMEM_TOTAL (STAGES * STAGE_BYTES)         // 49152 -> 4 CTAs/SM

#define SW(o) ((o) ^ (((o) >> 3) & 0x70))

// ---------------- device scratch ----------------
__device__ alignas(256) __half g_y[(size_t)NV * CC];      // fp16 activations (25.6 MB)
__device__ alignas(256) __half g_t16[(size_t)NV * CC];    // conv1 output fp16 (25.6 MB)
__device__ alignas(256) __half g_Wh[2][KK * CC * CC];     // fp16 weights, pre-swizzled
__device__ float g_sum[2][CC];
__device__ float g_sumsq[2][CC];
__device__ int   g_is64;

// ---------------- helpers ----------------
__device__ __forceinline__ uint32_t smem_u32(const void* p) {
    return (uint32_t)__cvta_generic_to_shared(p);
}
__device__ __forceinline__ void cp16(uint32_t dst, const void* src) {
    asm volatile("cp.async.cg.shared.global [%0], [%1], 16;\n" :: "r"(dst), "l"(src));
}
__device__ __forceinline__ int ld_idx(const void* nbr, bool is64, int gn, int k) {
    size_t pos = (size_t)gn * KK + k;
    return is64 ? (int)((const long long*)nbr)[pos] : ((const int*)nbr)[pos];
}

// ---------------- init + weight convert (fused) ----------------
__global__ void k_init_wcvt(const void* __restrict__ nbr,
                            const float* __restrict__ W1,
                            const float* __restrict__ W2) {
    if (blockIdx.x == 0) {
        int t = threadIdx.x;
        if (t < CC) {
            g_sum[0][t] = 0.f; g_sum[1][t] = 0.f;
            g_sumsq[0][t] = 0.f; g_sumsq[1][t] = 0.f;
        }
        if (t == 0) {
            const long long* p = (const long long*)nbr;
            int ok = 1;
            for (int i = 0; i < 64; ++i) {
                long long v = p[i];
                if (v < 0 || v >= NV) { ok = 0; break; }
            }
            g_is64 = ok;
        }
    }
    const int total = KK * CC * CC;
    for (int i = blockIdx.x * blockDim.x + threadIdx.x; i < total;
         i += gridDim.x * blockDim.x) {
        int k  = i >> 12;
        int ci = (i & 4095) >> 6;
        int co = i & 63;
        uint32_t off = (uint32_t)SW(ci * 128 + co * 2) >> 1;
        g_Wh[0][k * 4096 + off] = __float2half_rn(W1[i]);
        g_Wh[1][k * 4096 + off] = __float2half_rn(W2[i]);
    }
}

// ---------------- per-channel sum / sumsq (stage0: f32 x, stage1: f16 g_t16) ----------------
__global__ void k_colstats(const float* __restrict__ xin, int stage) {
    __shared__ float sh[2][4][CC];
    int ch = threadIdx.x & 63;
    int rg = threadIdx.x >> 6;
    float s = 0.f, s2 = 0.f;
    if (stage == 0) {
        for (int row = blockIdx.x * 4 + rg; row < NV; row += gridDim.x * 4) {
            float x = xin[(size_t)row * CC + ch];
            s += x; s2 += x * x;
        }
    } else {
        for (int row = blockIdx.x * 4 + rg; row < NV; row += gridDim.x * 4) {
            float x = __half2float(g_t16[(size_t)row * CC + ch]);
            s += x; s2 += x * x;
        }
    }
    sh[0][rg][ch] = s; sh[1][rg][ch] = s2;
    __syncthreads();
    if (rg == 0) {
        s  = sh[0][0][ch] + sh[0][1][ch] + sh[0][2][ch] + sh[0][3][ch];
        s2 = sh[1][0][ch] + sh[1][1][ch] + sh[1][2][ch] + sh[1][3][ch];
        atomicAdd(&g_sum[stage][ch], s);
        atomicAdd(&g_sumsq[stage][ch], s2);
    }
}

// ---------------- fused finalize + BN + ReLU + fp16 quantize ----------------
__global__ void k_bnrelu(const float* __restrict__ xin,
                         const float* __restrict__ gamma,
                         const float* __restrict__ beta, int stage) {
    __shared__ float s_scale[CC], s_shift[CC];
    if (threadIdx.x < CC) {
        int c = threadIdx.x;
        float mean = g_sum[stage][c] / (float)NV;
        float var  = g_sumsq[stage][c] / (float)NV - mean * mean;
        float s = gamma[c] * rsqrtf(var + BN_EPS);
        s_scale[c] = s;
        s_shift[c] = beta[c] - mean * s;
    }
    __syncthreads();
    const int total = NV * CC / 4;
    for (int i = blockIdx.x * blockDim.x + threadIdx.x; i < total;
         i += gridDim.x * blockDim.x) {
        int cb = (i & 15) << 2;
        float f0, f1, f2, f3;
        if (stage == 0) {
            float4 f = ((const float4*)xin)[i];
            f0 = f.x; f1 = f.y; f2 = f.z; f3 = f.w;
        } else {
            uint2 u = ((const uint2*)g_t16)[i];
            __half2 h0 = *(__half2*)&u.x;
            __half2 h1 = *(__half2*)&u.y;
            float2 p0 = __half22float2(h0);
            float2 p1 = __half22float2(h1);
            f0 = p0.x; f1 = p0.y; f2 = p1.x; f3 = p1.y;
        }
        float a = fmaxf(fmaf(f0, s_scale[cb + 0], s_shift[cb + 0]), 0.f);
        float b = fmaxf(fmaf(f1, s_scale[cb + 1], s_shift[cb + 1]), 0.f);
        float c = fmaxf(fmaf(f2, s_scale[cb + 2], s_shift[cb + 2]), 0.f);
        float d = fmaxf(fmaf(f3, s_scale[cb + 3], s_shift[cb + 3]), 0.f);
        ((__half2*)g_y)[2 * i]     = __floats2half2_rn(a, b);
        ((__half2*)g_y)[2 * i + 1] = __floats2half2_rn(c, d);
    }
}

// ---------------- pipelined gather-GEMM conv (HMMA, 2-stage, occ 4) ----------------
__global__ void __launch_bounds__(256, 4)
k_conv(const void* __restrict__ nbr, int which,
       const float* __restrict__ residual, float* __restrict__ dout)
{
    extern __shared__ char smem[];
    const uint32_t sb = smem_u32(smem);

    const __half* __restrict__ Wh = g_Wh[which];

    const int tid = threadIdx.x;
    const int warp = tid >> 5, lane = tid & 31;
    const int wm = warp >> 1;
    const int wn = warp & 1;
    const int m0 = blockIdx.x * BM;
    const bool is64 = (g_is64 != 0);

    float acc[2][4][4];
    #pragma unroll
    for (int a = 0; a < 2; ++a)
        #pragma unroll
        for (int b = 0; b < 4; ++b)
            #pragma unroll
            for (int c = 0; c < 4; ++c) acc[a][b][c] = 0.f;

    const int r  = tid >> 1;
    const int hs = tid & 1;
    const int gn = (m0 + r < NV) ? (m0 + r) : 0;

    auto fill = [&](int st, int gi, int k) {
        const __half* srcA = g_y + (size_t)gi * CC + hs * 32;
        uint32_t abase = sb + st * STAGE_BYTES;
        #pragma unroll
        for (int j = 0; j < 4; ++j) {
            uint32_t boff = (uint32_t)(r * 128 + (hs * 4 + j) * 16);
            cp16(abase + SW(boff), srcA + j * 8);
        }
        const __half* srcB = Wh + k * 4096;
        uint32_t bbase = abase + A_BYTES;
        cp16(bbase + tid * 16,         srcB + tid * 8);
        cp16(bbase + (tid + 256) * 16, srcB + (tid + 256) * 8);
    };

    // prologue: fill stage0(k=0), stage1(k=1)
    {
        int i0 = ld_idx(nbr, is64, gn, 0);
        int i1 = ld_idx(nbr, is64, gn, 1);
        fill(0, i0, 0);
        asm volatile("cp.async.commit_group;\n");
        fill(1, i1, 1);
        asm volatile("cp.async.commit_group;\n");
    }
    int gi_next = ld_idx(nbr, is64, gn, 2);

    for (int k = 0; k < KK; ++k) {
        const int st = k & 1;
        if (k + 1 < KK)
            asm volatile("cp.async.wait_group 1;\n");
        else
            asm volatile("cp.async.wait_group 0;\n");
        __syncthreads();

        const uint32_t abase = sb + st * STAGE_BYTES;
        const uint32_t bbase = abase + A_BYTES;

        #pragma unroll
        for (int ks = 0; ks < 4; ++ks) {
            const int k0 = ks * 16;
            uint32_t a0[4], a1[4];
            {
                int row = wm * 32 + (lane & 15);
                int col = k0 + (lane >> 4) * 8;
                uint32_t ad = abase + SW((uint32_t)(row * 128 + col * 2));
                asm volatile("ldmatrix.sync.aligned.m8n8.x4.shared.b16 {%0,%1,%2,%3}, [%4];"
                             : "=r"(a0[0]), "=r"(a0[1]), "=r"(a0[2]), "=r"(a0[3]) : "r"(ad));
                ad = abase + SW((uint32_t)((row + 16) * 128 + col * 2));
                asm volatile("ldmatrix.sync.aligned.m8n8.x4.shared.b16 {%0,%1,%2,%3}, [%4];"
                             : "=r"(a1[0]), "=r"(a1[1]), "=r"(a1[2]), "=r"(a1[3]) : "r"(ad));
            }
            uint32_t b0[4], b1[4];
            {
                int krow = k0 + ((lane >> 3) & 1) * 8 + (lane & 7);
                int coll = wn * 32 + (lane >> 4) * 8;
                uint32_t ad = bbase + SW((uint32_t)(krow * 128 + coll * 2));
                asm volatile("ldmatrix.sync.aligned.m8n8.x4.trans.shared.b16 {%0,%1,%2,%3}, [%4];"
                             : "=r"(b0[0]), "=r"(b0[1]), "=r"(b0[2]), "=r"(b0[3]) : "r"(ad));
                ad = bbase + SW((uint32_t)(krow * 128 + (coll + 16) * 2));
                asm volatile("ldmatrix.sync.aligned.m8n8.x4.trans.shared.b16 {%0,%1,%2,%3}, [%4];"
                             : "=r"(b1[0]), "=r"(b1[1]), "=r"(b1[2]), "=r"(b1[3]) : "r"(ad));
            }
            #pragma unroll
            for (int mt = 0; mt < 2; ++mt) {
                const uint32_t* A = mt ? a1 : a0;
                #pragma unroll
                for (int nt = 0; nt < 4; ++nt) {
                    const uint32_t* B = (nt < 2) ? b0 : b1;
                    uint32_t bb0 = B[(nt & 1) * 2], bb1 = B[(nt & 1) * 2 + 1];
                    float* C = acc[mt][nt];
                    asm volatile(
                        "mma.sync.aligned.m16n8k16.row.col.f32.f16.f16.f32 "
                        "{%0,%1,%2,%3}, {%4,%5,%6,%7}, {%8,%9}, {%0,%1,%2,%3};"
                        : "+f"(C[0]), "+f"(C[1]), "+f"(C[2]), "+f"(C[3])
                        : "r"(A[0]), "r"(A[1]), "r"(A[2]), "r"(A[3]),
                          "r"(bb0), "r"(bb1));
                }
            }
        }

        // refill this stage with k+2 after compute is done
        if (k + 2 < KK) {
            __syncthreads();
            fill(st, gi_next, k + 2);
            asm volatile("cp.async.commit_group;\n");
            gi_next = ld_idx(nbr, is64, gn, (k + 3 < KK) ? (k + 3) : (KK - 1));
        }
    }

    // ---- epilogue ----
    if (which == 0) {
        // conv1: write fp16 to g_t16
        #pragma unroll
        for (int mt = 0; mt < 2; ++mt) {
            int rbase = m0 + wm * 32 + mt * 16 + (lane >> 2);
            #pragma unroll
            for (int nt = 0; nt < 4; ++nt) {
                int col = wn * 32 + nt * 8 + (lane & 3) * 2;
                float* C = acc[mt][nt];
                if (rbase < NV) {
                    size_t o = (size_t)rbase * CC + col;
                    *(__half2*)(g_t16 + o) = __floats2half2_rn(C[0], C[1]);
                }
                if (rbase + 8 < NV) {
                    size_t o = (size_t)(rbase + 8) * CC + col;
                    *(__half2*)(g_t16 + o) = __floats2half2_rn(C[2], C[3]);
                }
            }
        }
    } else {
        // conv2: fp32 out + residual
        #pragma unroll
        for (int mt = 0; mt < 2; ++mt) {
            int rbase = m0 + wm * 32 + mt * 16 + (lane >> 2);
            #pragma unroll
            for (int nt = 0; nt < 4; ++nt) {
                int col = wn * 32 + nt * 8 + (lane & 3) * 2;
                float* C = acc[mt][nt];
                if (rbase < NV) {
                    size_t o = (size_t)rbase * CC + col;
                    dout[o]     = C[0] + residual[o];
                    dout[o + 1] = C[1] + residual[o + 1];
                }
                if (rbase + 8 < NV) {
                    size_t o = (size_t)(rbase + 8) * CC + col;
                    dout[o]     = C[2] + residual[o];
                    dout[o + 1] = C[3] + residual[o + 1];
                }
            }
        }
    }
}

// ---------------- launch ----------------
extern "C" void kernel_launch(void* const* d_in, const int* in_sizes, int n_in,
                              void* d_out, int out_size) {
    const float* x      = (const float*)d_in[0];
    const void*  nbr    = d_in[1];
    const float* W1     = (const float*)d_in[2];
    const float* gamma1 = (const float*)d_in[3];
    const float* beta1  = (const float*)d_in[4];
    const float* W2     = (const float*)d_in[5];
    const float* gamma2 = (const float*)d_in[6];
    const float* beta2  = (const float*)d_in[7];
    float* out = (float*)d_out;

    const int conv_grid = (NV + BM - 1) / BM;

    static int attr_set = 0;
    if (!attr_set) {
        cudaFuncSetAttribute(k_conv, cudaFuncAttributeMaxDynamicSharedMemorySize,
                             SMEM_TOTAL);
        attr_set = 1;
    }

    k_init_wcvt<<<432, 256>>>(nbr, W1, W2);                       // launch 1
    k_colstats<<<512, 256>>>(x, 0);                               // launch 2
    k_bnrelu<<<2048, 256>>>(x, gamma1, beta1, 0);                 // launch 3
    k_conv<<<conv_grid, 256, SMEM_TOTAL>>>(nbr, 0, nullptr, nullptr); // launch 4 <- ncu
    k_colstats<<<512, 256>>>(nullptr, 1);                         // launch 5
    k_bnrelu<<<2048, 256>>>(nullptr, gamma2, beta2, 1);           // launch 6
    k_conv<<<conv_grid, 256, SMEM_TOTAL>>>(nbr, 1, x, out);       // launch 7
}